// round 9
// baseline (speedup 1.0000x reference)
#include <cuda_runtime.h>
#include <math.h>

#define NB 8192
#define NV 101
#define NT 30
#define NC 4
#define ND 64
#define NH 128
#define NVP 112     // padded row count (zeroed pad rows 101..111)
#define KD  104     // dyn k-dim padding / row stride (zeroed cols 101..103)
#define NTHR 448    // 14 warps

typedef unsigned long long u64;

// Scratch (static device arrays: allowed; no cudaMalloc anywhere)
__device__ float g_h[(size_t)NB * NV * ND];   // final hidden states (B, V*64)
__device__ float g_y[(size_t)NB * NH];        // relu(flat @ Wf1 + bf1)

// ---------------- SMEM layout (floats) ----------------
#define OFF_W2   0                       // 64*64    = 4096
#define OFF_WZ   (OFF_W2 + 4096)         // 132*64   = 8448
#define OFF_WR   (OFF_WZ + 8448)
#define OFF_WW   (OFF_WR + 8448)
#define OFF_W1   (OFF_WW + 8448)         // 4*64     = 256
#define OFF_H    (OFF_W1 + 256)          // 112*64   = 7168
#define OFF_WK   (OFF_H + 7168)          // 7168
#define OFF_DYN  (OFF_WK + 7168)         // 112*104  = 11648
#define OFF_XT   (OFF_DYN + 11648)       // 112*4    = 448
#define OFF_AGG  (OFF_XT + 448)          // 448
#define OFF_B1   (OFF_AGG + 448)
#define OFF_B2   (OFF_B1 + 64)
#define OFF_BZ   (OFF_B2 + 64)
#define OFF_BR   (OFF_BZ + 64)
#define OFF_BW   (OFF_BR + 64)
#define SMEM_FLOATS (OFF_BW + 64)        // 56,896 floats
#define SMEM_BYTES (SMEM_FLOATS * 4)     // 227,584 B <= 232,448 cap

// ---- fast activations (MUFU ex2/rcp; ~1e-6 rel err, gate is 1e-3) ----
__device__ __forceinline__ float ex2f(float x) {
    float y; asm("ex2.approx.f32 %0, %1;" : "=f"(y) : "f"(x)); return y;
}
__device__ __forceinline__ float rcpf(float x) {
    float y; asm("rcp.approx.f32 %0, %1;" : "=f"(y) : "f"(x)); return y;
}
#define LOG2E_F 1.4426950408889634f
__device__ __forceinline__ float sigm(float v) {
    return rcpf(1.0f + ex2f(-v * LOG2E_F));
}
__device__ __forceinline__ float tanh_fast(float v) {
    return 1.0f - 2.0f * rcpf(1.0f + ex2f(v * (2.0f * LOG2E_F)));
}

// ---- packed f32x2 primitives (exact fp32 RN, 2 FMAs/instr) ----
__device__ __forceinline__ u64 pk2(float lo, float hi) {
    u64 r; asm("mov.b64 %0, {%1, %2};" : "=l"(r) : "f"(lo), "f"(hi)); return r;
}
__device__ __forceinline__ void upk2(float& lo, float& hi, u64 v) {
    asm("mov.b64 {%0, %1}, %2;" : "=f"(lo), "=f"(hi) : "l"(v));
}
__device__ __forceinline__ u64 ffma2(u64 a, u64 b, u64 c) {
    u64 d; asm("fma.rn.f32x2 %0, %1, %2, %3;" : "=l"(d) : "l"(a), "l"(b), "l"(c));
    return d;
}

// acc[4 rows][2 u64 = 4 cols] += act[rbase+r][k] * W[k][c0..c0+3]
// W row stride fixed 64 floats. K multiple of 4. All pointers 16B aligned.
__device__ __forceinline__ void gemmT(u64 acc[4][2],
    const float* __restrict__ act, int stride, int rbase,
    const float* __restrict__ W, int K, int c0)
{
    const float* wp = W + c0;
#pragma unroll 2
    for (int k = 0; k < K; k += 4) {
        float4 av[4];
#pragma unroll
        for (int r = 0; r < 4; ++r)
            av[r] = *reinterpret_cast<const float4*>(act + (rbase + r) * stride + k);
#pragma unroll
        for (int kk = 0; kk < 4; ++kk) {
            ulonglong2 wv = *reinterpret_cast<const ulonglong2*>(wp + (k + kk) * 64);
#pragma unroll
            for (int r = 0; r < 4; ++r) {
                float a = reinterpret_cast<const float*>(&av[r])[kk];
                u64 ad = pk2(a, a);
                acc[r][0] = ffma2(ad, wv.x, acc[r][0]);
                acc[r][1] = ffma2(ad, wv.y, acc[r][1]);
            }
        }
    }
}

__device__ __forceinline__ void bias4(u64 acc[4][2], const float* bb, int c0) {
    u64 t0 = pk2(bb[c0],     bb[c0 + 1]);
    u64 t1 = pk2(bb[c0 + 2], bb[c0 + 3]);
#pragma unroll
    for (int r = 0; r < 4; ++r) { acc[r][0] = t0; acc[r][1] = t1; }
}

__device__ __forceinline__ void zero4(u64 acc[4][2]) {
    u64 z = pk2(0.0f, 0.0f);
#pragma unroll
    for (int r = 0; r < 4; ++r) { acc[r][0] = z; acc[r][1] = z; }
}

__global__ __launch_bounds__(NTHR, 1)
void mgcgru_scan(const float* __restrict__ x,
                 const float* __restrict__ dyn,
                 const float* __restrict__ W1, const float* __restrict__ b1,
                 const float* __restrict__ W2, const float* __restrict__ b2,
                 const float* __restrict__ Wz, const float* __restrict__ bz,
                 const float* __restrict__ Wr, const float* __restrict__ br,
                 const float* __restrict__ Ww, const float* __restrict__ bw)
{
    extern __shared__ float sm[];
    float* sW2  = sm + OFF_W2;
    float* sWz  = sm + OFF_WZ;
    float* sWr  = sm + OFF_WR;
    float* sWw  = sm + OFF_WW;
    float* sW1  = sm + OFF_W1;
    float* sh   = sm + OFF_H;
    float* swk  = sm + OFF_WK;
    float* sdyn = sm + OFF_DYN;
    float* sxt  = sm + OFF_XT;
    float* sagg = sm + OFF_AGG;
    float* sb1  = sm + OFF_B1;
    float* sb2  = sm + OFF_B2;
    float* sbz  = sm + OFF_BZ;
    float* sbr  = sm + OFF_BR;
    float* sbw  = sm + OFF_BW;

    const int tid = threadIdx.x;
    const int b   = blockIdx.x;

    // preload weights; zero-pad dyn to 112 rows x 104 cols
    for (int i = tid; i < NVP * KD; i += NTHR) {
        int u = i / KD, v = i - u * KD;
        sdyn[i] = (u < NV && v < NV) ? dyn[u * NV + v] : 0.0f;
    }
    for (int i = tid; i < NC * ND; i += NTHR) sW1[i] = W1[i];
    for (int i = tid; i < ND * ND; i += NTHR) sW2[i] = W2[i];
    for (int i = tid; i < 132 * ND; i += NTHR) {
        sWz[i] = Wz[i]; sWr[i] = Wr[i]; sWw[i] = Ww[i];
    }
    if (tid < ND) {
        sb1[tid] = b1[tid]; sb2[tid] = b2[tid];
        sbz[tid] = bz[tid]; sbr[tid] = br[tid]; sbw[tid] = bw[tid];
    }
    // zero full padded state (pad rows must be 0 and stay 0)
    for (int i = tid; i < NVP * ND; i += NTHR) { sh[i] = 0.0f; swk[i] = 0.0f; }
    for (int i = tid; i < NVP * NC; i += NTHR) { sxt[i] = 0.0f; sagg[i] = 0.0f; }

    // ownership: warp w covers rows [w*8, w*8+8); lane half lr picks 4 rows;
    // lane col-group lc picks 4 consecutive cols. 14 warps x 8 = 112 rows.
    const int w    = tid >> 5;
    const int lane = tid & 31;
    const int lr   = lane >> 4;        // 0..1
    const int lc   = lane & 15;        // 0..15
    const int c0   = lc * 4;
    const int rbase = w * 8 + lr * 4;  // 0,4,8,...,108

    __syncthreads();

    for (int t = 0; t < NT; ++t) {
        // load x_t slice (101 x 4)
        if (tid < NV) {
            float4 xv = *reinterpret_cast<const float4*>(
                x + (((size_t)b * NV + tid) * NT + t) * NC);
            *reinterpret_cast<float4*>(sxt + tid * 4) = xv;
        }
        __syncthreads();

        // stage1: agg[u][c] = sum_v dyn[u][v] * xt[v][c]  (tiny)
        if (tid < NV * NC) {
            int uu = tid >> 2, c = tid & 3;
            const float* dr = sdyn + uu * KD;
            float s = 0.0f;
#pragma unroll 4
            for (int v = 0; v < NV; ++v) s = fmaf(dr[v], sxt[v * 4 + c], s);
            sagg[tid] = s;
        }
        __syncthreads();

        // stage2: f1 = tanh(agg @ W1 + b1) -> swk
        {
            u64 acc[4][2];
            bias4(acc, sb1, c0);
            gemmT(acc, sagg, 4, rbase, sW1, 4, c0);
#pragma unroll
            for (int r = 0; r < 4; ++r) {
                int row = rbase + r;
                if (row < NV) {
                    float o0, o1, o2, o3;
                    upk2(o0, o1, acc[r][0]); upk2(o2, o3, acc[r][1]);
                    *reinterpret_cast<float4*>(swk + row * 64 + c0) =
                        make_float4(tanh_fast(o0), tanh_fast(o1), tanh_fast(o2), tanh_fast(o3));
                }
            }
        }
        __syncthreads();

        // stage3: agg2 = dyn @ f1 (K padded to 104; pad rows of swk are zero)
        {
            u64 acc[4][2];
            zero4(acc);
            gemmT(acc, sdyn, KD, rbase, swk, KD, c0);
            __syncthreads();   // all reads of f1 complete
#pragma unroll
            for (int r = 0; r < 4; ++r) {
                int row = rbase + r;
                if (row < NV) {
                    float o0, o1, o2, o3;
                    upk2(o0, o1, acc[r][0]); upk2(o2, o3, acc[r][1]);
                    *reinterpret_cast<float4*>(swk + row * 64 + c0) =
                        make_float4(o0, o1, o2, o3);
                }
            }
        }
        __syncthreads();

        // stage4: f = tanh(agg2 @ W2 + b2) -> swk (reg-staged overwrite)
        {
            u64 acc[4][2];
            bias4(acc, sb2, c0);
            gemmT(acc, swk, 64, rbase, sW2, 64, c0);
            __syncthreads();   // all reads of agg2 complete
#pragma unroll
            for (int r = 0; r < 4; ++r) {
                int row = rbase + r;
                if (row < NV) {
                    float o0, o1, o2, o3;
                    upk2(o0, o1, acc[r][0]); upk2(o2, o3, acc[r][1]);
                    *reinterpret_cast<float4*>(swk + row * 64 + c0) =
                        make_float4(tanh_fast(o0), tanh_fast(o1), tanh_fast(o2), tanh_fast(o3));
                }
            }
        }
        __syncthreads();

        // gates. cat = [xt(4) | f(64) | h(64)]
        float zf[4][4];
        float rh[4][4];
        u64 wacc[4][2];
        {
            u64 acc[4][2];
            bias4(acc, sbz, c0);
            gemmT(acc, sxt, 4,  rbase, sWz,           4,   c0);
            gemmT(acc, swk, 64, rbase, sWz + 4 * 64,  64,  c0);
            gemmT(acc, sh,  64, rbase, sWz + 68 * 64, 64,  c0);
#pragma unroll
            for (int r = 0; r < 4; ++r) {
                upk2(zf[r][0], zf[r][1], acc[r][0]);
                upk2(zf[r][2], zf[r][3], acc[r][1]);
#pragma unroll
                for (int j = 0; j < 4; ++j) zf[r][j] = sigm(zf[r][j]);
            }
        }
        {
            u64 acc[4][2];
            bias4(acc, sbr, c0);
            gemmT(acc, sxt, 4,  rbase, sWr,           4,   c0);
            gemmT(acc, swk, 64, rbase, sWr + 4 * 64,  64,  c0);
            gemmT(acc, sh,  64, rbase, sWr + 68 * 64, 64,  c0);
#pragma unroll
            for (int r = 0; r < 4; ++r) {
                upk2(rh[r][0], rh[r][1], acc[r][0]);
                upk2(rh[r][2], rh[r][3], acc[r][1]);
                float4 hv = *reinterpret_cast<const float4*>(sh + (rbase + r) * 64 + c0);
                rh[r][0] = sigm(rh[r][0]) * hv.x;
                rh[r][1] = sigm(rh[r][1]) * hv.y;
                rh[r][2] = sigm(rh[r][2]) * hv.z;
                rh[r][3] = sigm(rh[r][3]) * hv.w;
            }
        }
        bias4(wacc, sbw, c0);
        gemmT(wacc, sxt, 4,  rbase, sWw,          4,  c0);
        gemmT(wacc, swk, 64, rbase, sWw + 4 * 64, 64, c0);

        __syncthreads();   // all reads of f and h (by other lanes) complete
        // write r*h over swk (pad rows stay zero: guarded)
#pragma unroll
        for (int r = 0; r < 4; ++r) {
            int row = rbase + r;
            if (row < NV)
                *reinterpret_cast<float4*>(swk + row * 64 + c0) =
                    make_float4(rh[r][0], rh[r][1], rh[r][2], rh[r][3]);
        }
        __syncthreads();

        // stage7: wpre += (r*h) @ Ww_h ; h = h + z*(tanh(wpre) - h)
        gemmT(wacc, swk, 64, rbase, sWw + 68 * 64, 64, c0);
#pragma unroll
        for (int r = 0; r < 4; ++r) {
            int row = rbase + r;
            if (row < NV) {
                float o0, o1, o2, o3;
                upk2(o0, o1, wacc[r][0]); upk2(o2, o3, wacc[r][1]);
                float* hp = sh + row * 64 + c0;
                float4 hv = *reinterpret_cast<const float4*>(hp);
                float n0 = hv.x + zf[r][0] * (tanh_fast(o0) - hv.x);
                float n1 = hv.y + zf[r][1] * (tanh_fast(o1) - hv.y);
                float n2 = hv.z + zf[r][2] * (tanh_fast(o2) - hv.z);
                float n3 = hv.w + zf[r][3] * (tanh_fast(o3) - hv.w);
                *reinterpret_cast<float4*>(hp) = make_float4(n0, n1, n2, n3);
            }
        }
        // top-of-loop barriers order h writes vs next reads
    }

    __syncthreads();
    for (int i = tid; i < NV * ND; i += NTHR)
        g_h[(size_t)b * (NV * ND) + i] = sh[i];
}

// ---------------- FC1: g_y = relu(g_h @ Wf1 + bf1), M=8192 K=6464 N=128 ----
__global__ __launch_bounds__(256, 2)
void fc1_kernel(const float* __restrict__ Wf1, const float* __restrict__ bf1)
{
    __shared__ float sA[64 * 16];
    __shared__ float sB[16 * 128];
    const int tid = threadIdx.x;
    const int m0  = blockIdx.x * 64;
    const int tn  = tid & 31;   // 0..31 -> 4 cols each
    const int tm  = tid >> 5;   // 0..7  -> 8 rows each

    float acc[8][4];
#pragma unroll
    for (int i = 0; i < 8; ++i)
#pragma unroll
        for (int j = 0; j < 4; ++j) acc[i][j] = 0.0f;

    const int ai = tid >> 2, ak = (tid & 3) * 4;
    const int bk = tid >> 4, bn = (tid & 15) * 8;

    for (int k0 = 0; k0 < NV * ND; k0 += 16) {
        *reinterpret_cast<float4*>(&sA[ai * 16 + ak]) =
            *reinterpret_cast<const float4*>(&g_h[(size_t)(m0 + ai) * (NV * ND) + k0 + ak]);
        *reinterpret_cast<float4*>(&sB[bk * 128 + bn]) =
            *reinterpret_cast<const float4*>(&Wf1[(size_t)(k0 + bk) * 128 + bn]);
        *reinterpret_cast<float4*>(&sB[bk * 128 + bn + 4]) =
            *reinterpret_cast<const float4*>(&Wf1[(size_t)(k0 + bk) * 128 + bn + 4]);
        __syncthreads();
#pragma unroll
        for (int kk = 0; kk < 16; ++kk) {
            float bv[4];
            *reinterpret_cast<float4*>(bv) =
                *reinterpret_cast<const float4*>(&sB[kk * 128 + tn * 4]);
#pragma unroll
            for (int i = 0; i < 8; ++i) {
                float av = sA[(tm * 8 + i) * 16 + kk];
                acc[i][0] = fmaf(av, bv[0], acc[i][0]);
                acc[i][1] = fmaf(av, bv[1], acc[i][1]);
                acc[i][2] = fmaf(av, bv[2], acc[i][2]);
                acc[i][3] = fmaf(av, bv[3], acc[i][3]);
            }
        }
        __syncthreads();
    }
#pragma unroll
    for (int i = 0; i < 8; ++i) {
        int m = m0 + tm * 8 + i;
#pragma unroll
        for (int j = 0; j < 4; ++j) {
            int n = tn * 4 + j;
            g_y[(size_t)m * 128 + n] = fmaxf(acc[i][j] + bf1[n], 0.0f);
        }
    }
}

// ---------------- head: out = softmax(g_y @ Wf2 + bf2) ----------------
__global__ __launch_bounds__(128)
void head_kernel(const float* __restrict__ Wf2, const float* __restrict__ bf2,
                 float* __restrict__ out)
{
    const int b = blockIdx.x, tid = threadIdx.x;
    __shared__ float sy[128];
    __shared__ float red[128];

    sy[tid] = g_y[(size_t)b * 128 + tid];
    __syncthreads();

    float logit = -3.0e38f;
    if (tid < NV) {
        float s = bf2[tid];
#pragma unroll 4
        for (int k = 0; k < 128; ++k) s = fmaf(sy[k], Wf2[k * NV + tid], s);
        logit = s;
    }
    red[tid] = logit;
    __syncthreads();
#pragma unroll
    for (int off = 64; off > 0; off >>= 1) {
        if (tid < off) red[tid] = fmaxf(red[tid], red[tid + off]);
        __syncthreads();
    }
    float m = red[0];
    __syncthreads();
    float e = (tid < NV) ? expf(logit - m) : 0.0f;
    red[tid] = e;
    __syncthreads();
#pragma unroll
    for (int off = 64; off > 0; off >>= 1) {
        if (tid < off) red[tid] += red[tid + off];
        __syncthreads();
    }
    float s = red[0];
    if (tid < NV) out[(size_t)b * NV + tid] = e / s;
}

extern "C" void kernel_launch(void* const* d_in, const int* in_sizes, int n_in,
                              void* d_out, int out_size)
{
    (void)in_sizes; (void)n_in; (void)out_size;
    const float* x   = (const float*)d_in[0];
    const float* dyn = (const float*)d_in[1];
    const float* W1  = (const float*)d_in[2];
    const float* b1  = (const float*)d_in[3];
    const float* W2  = (const float*)d_in[4];
    const float* b2  = (const float*)d_in[5];
    const float* Wz  = (const float*)d_in[6];
    const float* bz  = (const float*)d_in[7];
    const float* Wr  = (const float*)d_in[8];
    const float* br  = (const float*)d_in[9];
    const float* Ww  = (const float*)d_in[10];
    const float* bw  = (const float*)d_in[11];
    const float* Wf1 = (const float*)d_in[12];
    const float* bf1 = (const float*)d_in[13];
    const float* Wf2 = (const float*)d_in[14];
    const float* bf2 = (const float*)d_in[15];
    float* out = (float*)d_out;

    cudaFuncSetAttribute(mgcgru_scan, cudaFuncAttributeMaxDynamicSharedMemorySize, SMEM_BYTES);
    mgcgru_scan<<<NB, NTHR, SMEM_BYTES>>>(x, dyn, W1, b1, W2, b2, Wz, bz, Wr, br, Ww, bw);
    fc1_kernel<<<NB / 64, 256>>>(Wf1, bf1);
    head_kernel<<<NB, 128>>>(Wf2, bf2, out);
}

// round 12
// speedup vs baseline: 1.0754x; 1.0754x over previous
#include <cuda_runtime.h>
#include <math.h>

#define NB 8192
#define NV 101
#define NT 30
#define NC 4
#define ND 64
#define NH 128
#define NVP 104     // padded row count (zeroed pad rows 101..103)
#define DSTR 104    // padded dyn row stride (16B-aligned float4 rows)

typedef unsigned long long u64;

// Scratch (static device arrays: allowed; no cudaMalloc anywhere)
__device__ float g_h[(size_t)NB * NV * ND];   // final hidden states (B, V*64)
__device__ float g_y[(size_t)NB * NH];        // relu(flat @ Wf1 + bf1)

// ---------------- SMEM layout (floats) ----------------
#define OFF_W2   0          // 64*64    = 4096
#define OFF_WZ   4096       // 132*64   = 8448
#define OFF_WR   12544      // 8448
#define OFF_WW   20992      // 8448
#define OFF_W1   29440      // 4*64     = 256
#define OFF_H    29696      // 104*64   = 6656
#define OFF_WK   36352      // 104*64   = 6656
#define OFF_DYN  43008      // 104*104  = 10816
#define OFF_XT   53824      // 104*4    = 416
#define OFF_AGG  54240      // 416
#define OFF_B1   54656
#define OFF_B2   54720
#define OFF_BZ   54784
#define OFF_BR   54848
#define OFF_BW   54912
#define SMEM_FLOATS 54976
#define SMEM_BYTES (SMEM_FLOATS * 4)   // 219,904 B

// ---- fast activations (MUFU ex2/rcp; validated R9: rel_err 8.3e-8) ----
__device__ __forceinline__ float ex2f(float x) {
    float y; asm("ex2.approx.f32 %0, %1;" : "=f"(y) : "f"(x)); return y;
}
__device__ __forceinline__ float rcpf(float x) {
    float y; asm("rcp.approx.f32 %0, %1;" : "=f"(y) : "f"(x)); return y;
}
#define LOG2E_F 1.4426950408889634f
__device__ __forceinline__ float sigm(float v) {
    return rcpf(1.0f + ex2f(-v * LOG2E_F));
}
__device__ __forceinline__ float tanh_fast(float v) {
    return 1.0f - 2.0f * rcpf(1.0f + ex2f(v * (2.0f * LOG2E_F)));
}

// ---- packed f32x2 primitives (exact fp32 RN, 2 FMAs/instr) ----
__device__ __forceinline__ u64 pk2(float lo, float hi) {
    u64 r; asm("mov.b64 %0, {%1, %2};" : "=l"(r) : "f"(lo), "f"(hi)); return r;
}
__device__ __forceinline__ void upk2(float& lo, float& hi, u64 v) {
    asm("mov.b64 {%0, %1}, %2;" : "=f"(lo), "=f"(hi) : "l"(v));
}
__device__ __forceinline__ u64 ffma2(u64 a, u64 b, u64 c) {
    u64 d; asm("fma.rn.f32x2 %0, %1, %2, %3;" : "=l"(d) : "l"(a), "l"(b), "l"(c));
    return d;
}

// acc[7 rows][2 u64 = 4 cols] += act[rbase+r][k] * W[k][c0..c0+3]
// W row stride fixed 64 floats. K multiple of 4. All pointers 16B aligned.
__device__ __forceinline__ void gemmT(u64 acc[7][2],
    const float* __restrict__ act, int stride, int rbase,
    const float* __restrict__ W, int K, int c0)
{
    const float* wp = W + c0;
#pragma unroll 2
    for (int k = 0; k < K; k += 4) {
        float4 av[7];
#pragma unroll
        for (int r = 0; r < 7; ++r)
            av[r] = *reinterpret_cast<const float4*>(act + (rbase + r) * stride + k);
#pragma unroll
        for (int kk = 0; kk < 4; ++kk) {
            ulonglong2 wv = *reinterpret_cast<const ulonglong2*>(wp + (k + kk) * 64);
#pragma unroll
            for (int r = 0; r < 7; ++r) {
                float a = reinterpret_cast<const float*>(&av[r])[kk];
                u64 ad = pk2(a, a);
                acc[r][0] = ffma2(ad, wv.x, acc[r][0]);
                acc[r][1] = ffma2(ad, wv.y, acc[r][1]);
            }
        }
    }
}

// fused 3-matrix version: one act pass feeds z, r, w accumulators.
// Accumulation order per gate identical to 3 separate gemmT calls.
__device__ __forceinline__ void gemmT3(u64 aZ[7][2], u64 aR[7][2], u64 aW[7][2],
    const float* __restrict__ act, int stride, int rbase,
    const float* __restrict__ WZp, const float* __restrict__ WRp,
    const float* __restrict__ WWp, int K, int c0)
{
    const float* wz = WZp + c0;
    const float* wr = WRp + c0;
    const float* ww = WWp + c0;
#pragma unroll 1
    for (int k = 0; k < K; k += 4) {
        float4 av[7];
#pragma unroll
        for (int r = 0; r < 7; ++r)
            av[r] = *reinterpret_cast<const float4*>(act + (rbase + r) * stride + k);
#pragma unroll
        for (int kk = 0; kk < 4; ++kk) {
            ulonglong2 wvz = *reinterpret_cast<const ulonglong2*>(wz + (k + kk) * 64);
            ulonglong2 wvr = *reinterpret_cast<const ulonglong2*>(wr + (k + kk) * 64);
            ulonglong2 wvw = *reinterpret_cast<const ulonglong2*>(ww + (k + kk) * 64);
#pragma unroll
            for (int r = 0; r < 7; ++r) {
                float a = reinterpret_cast<const float*>(&av[r])[kk];
                u64 ad = pk2(a, a);
                aZ[r][0] = ffma2(ad, wvz.x, aZ[r][0]);
                aZ[r][1] = ffma2(ad, wvz.y, aZ[r][1]);
                aR[r][0] = ffma2(ad, wvr.x, aR[r][0]);
                aR[r][1] = ffma2(ad, wvr.y, aR[r][1]);
                aW[r][0] = ffma2(ad, wvw.x, aW[r][0]);
                aW[r][1] = ffma2(ad, wvw.y, aW[r][1]);
            }
        }
    }
}

// fused 2-matrix version (z, r over the h-segment)
__device__ __forceinline__ void gemmT2(u64 aZ[7][2], u64 aR[7][2],
    const float* __restrict__ act, int stride, int rbase,
    const float* __restrict__ WZp, const float* __restrict__ WRp, int K, int c0)
{
    const float* wz = WZp + c0;
    const float* wr = WRp + c0;
#pragma unroll 1
    for (int k = 0; k < K; k += 4) {
        float4 av[7];
#pragma unroll
        for (int r = 0; r < 7; ++r)
            av[r] = *reinterpret_cast<const float4*>(act + (rbase + r) * stride + k);
#pragma unroll
        for (int kk = 0; kk < 4; ++kk) {
            ulonglong2 wvz = *reinterpret_cast<const ulonglong2*>(wz + (k + kk) * 64);
            ulonglong2 wvr = *reinterpret_cast<const ulonglong2*>(wr + (k + kk) * 64);
#pragma unroll
            for (int r = 0; r < 7; ++r) {
                float a = reinterpret_cast<const float*>(&av[r])[kk];
                u64 ad = pk2(a, a);
                aZ[r][0] = ffma2(ad, wvz.x, aZ[r][0]);
                aZ[r][1] = ffma2(ad, wvz.y, aZ[r][1]);
                aR[r][0] = ffma2(ad, wvr.x, aR[r][0]);
                aR[r][1] = ffma2(ad, wvr.y, aR[r][1]);
            }
        }
    }
}

__device__ __forceinline__ void bias7(u64 acc[7][2], const float* bb, int c0) {
    u64 t0 = pk2(bb[c0],     bb[c0 + 1]);
    u64 t1 = pk2(bb[c0 + 2], bb[c0 + 3]);
#pragma unroll
    for (int r = 0; r < 7; ++r) { acc[r][0] = t0; acc[r][1] = t1; }
}

__device__ __forceinline__ void zero7(u64 acc[7][2]) {
    u64 z = pk2(0.0f, 0.0f);
#pragma unroll
    for (int r = 0; r < 7; ++r) { acc[r][0] = z; acc[r][1] = z; }
}

__global__ __launch_bounds__(256, 1)
void mgcgru_scan(const float* __restrict__ x,
                 const float* __restrict__ dyn,
                 const float* __restrict__ W1, const float* __restrict__ b1,
                 const float* __restrict__ W2, const float* __restrict__ b2,
                 const float* __restrict__ Wz, const float* __restrict__ bz,
                 const float* __restrict__ Wr, const float* __restrict__ br,
                 const float* __restrict__ Ww, const float* __restrict__ bw)
{
    extern __shared__ float sm[];
    float* sW2  = sm + OFF_W2;
    float* sWz  = sm + OFF_WZ;
    float* sWr  = sm + OFF_WR;
    float* sWw  = sm + OFF_WW;
    float* sW1  = sm + OFF_W1;
    float* sh   = sm + OFF_H;
    float* swk  = sm + OFF_WK;
    float* sdyn = sm + OFF_DYN;
    float* sxt  = sm + OFF_XT;
    float* sagg = sm + OFF_AGG;
    float* sb1  = sm + OFF_B1;
    float* sb2  = sm + OFF_B2;
    float* sbz  = sm + OFF_BZ;
    float* sbr  = sm + OFF_BR;
    float* sbw  = sm + OFF_BW;

    const int tid = threadIdx.x;
    const int b   = blockIdx.x;

    // preload weights; zero-pad dyn rows/cols to 104x104
    for (int i = tid; i < NVP * DSTR; i += 256) {
        int u = i / DSTR, v = i - u * DSTR;
        sdyn[i] = (u < NV && v < NV) ? dyn[u * NV + v] : 0.0f;
    }
    for (int i = tid; i < NC * ND; i += 256) sW1[i] = W1[i];
    for (int i = tid; i < ND * ND; i += 256) sW2[i] = W2[i];
    for (int i = tid; i < 132 * ND; i += 256) {
        sWz[i] = Wz[i]; sWr[i] = Wr[i]; sWw[i] = Ww[i];
    }
    if (tid < ND) {
        sb1[tid] = b1[tid]; sb2[tid] = b2[tid];
        sbz[tid] = bz[tid]; sbr[tid] = br[tid]; sbw[tid] = bw[tid];
    }
    // zero full padded state (pad rows must be 0 and stay 0)
    for (int i = tid; i < NVP * ND; i += 256) { sh[i] = 0.0f; swk[i] = 0.0f; }
    for (int i = tid; i < NVP * NC; i += 256) { sxt[i] = 0.0f; sagg[i] = 0.0f; }

    // ownership: warp w covers rows [w*14, w*14+14); lane half lr gives 7 rows;
    // lane col-group lc gives 4 consecutive cols. 8 warps x 14 = 112 >= 104.
    const int w    = tid >> 5;
    const int lane = tid & 31;
    const int lr   = lane >> 4;        // 0..1
    const int lc   = lane & 15;        // 0..15
    const int c0   = lc * 4;
    const int rbase = w * 14 + lr * 7; // 0,7,14,...,105

    __syncthreads();

    for (int t = 0; t < NT; ++t) {
        // load x_t slice (101 x 4)
        if (tid < NV) {
            float4 xv = *reinterpret_cast<const float4*>(
                x + (((size_t)b * NV + tid) * NT + t) * NC);
            *reinterpret_cast<float4*>(sxt + tid * 4) = xv;
        }
        __syncthreads();

        // stage1: agg[u][c] = sum_v dyn[u][v] * xt[v][c]  (tiny)
        for (int i = tid; i < NV * NC; i += 256) {
            int uu = i >> 2, c = i & 3;
            const float* dr = sdyn + uu * DSTR;
            float s = 0.0f;
#pragma unroll 4
            for (int v = 0; v < NV; ++v) s = fmaf(dr[v], sxt[v * 4 + c], s);
            sagg[i] = s;
        }
        __syncthreads();

        // stage2: f1 = tanh(agg @ W1 + b1) -> swk
        {
            u64 acc[7][2];
            bias7(acc, sb1, c0);
            gemmT(acc, sagg, 4, rbase, sW1, 4, c0);
#pragma unroll
            for (int r = 0; r < 7; ++r) {
                int row = rbase + r;
                if (row < NV) {
                    float o0, o1, o2, o3;
                    upk2(o0, o1, acc[r][0]); upk2(o2, o3, acc[r][1]);
                    *reinterpret_cast<float4*>(swk + row * 64 + c0) =
                        make_float4(tanh_fast(o0), tanh_fast(o1), tanh_fast(o2), tanh_fast(o3));
                }
            }
        }
        __syncthreads();

        // stage3: agg2 = dyn @ f1 (K padded to 104; pad rows of swk are zero)
        {
            u64 acc[7][2];
            zero7(acc);
            gemmT(acc, sdyn, DSTR, rbase, swk, NVP, c0);
            __syncthreads();   // all reads of f1 complete
#pragma unroll
            for (int r = 0; r < 7; ++r) {
                int row = rbase + r;
                if (row < NV) {
                    float o0, o1, o2, o3;
                    upk2(o0, o1, acc[r][0]); upk2(o2, o3, acc[r][1]);
                    *reinterpret_cast<float4*>(swk + row * 64 + c0) =
                        make_float4(o0, o1, o2, o3);
                }
            }
        }
        __syncthreads();

        // stage4: f = tanh(agg2 @ W2 + b2) -> swk (reg-staged overwrite)
        {
            u64 acc[7][2];
            bias7(acc, sb2, c0);
            gemmT(acc, swk, 64, rbase, sW2, 64, c0);
            __syncthreads();   // all reads of agg2 complete
#pragma unroll
            for (int r = 0; r < 7; ++r) {
                int row = rbase + r;
                if (row < NV) {
                    float o0, o1, o2, o3;
                    upk2(o0, o1, acc[r][0]); upk2(o2, o3, acc[r][1]);
                    *reinterpret_cast<float4*>(swk + row * 64 + c0) =
                        make_float4(tanh_fast(o0), tanh_fast(o1), tanh_fast(o2), tanh_fast(o3));
                }
            }
        }
        __syncthreads();

        // gates (fused). cat = [xt(4) | f(64) | h(64)]
        float zf[7][4];
        float rh[7][4];
        u64 wacc[7][2];
        {
            u64 zacc[7][2], racc[7][2];
            bias7(zacc, sbz, c0);
            bias7(racc, sbr, c0);
            bias7(wacc, sbw, c0);
            // x-segment (K=4): all 3 gates share one act pass
            gemmT3(zacc, racc, wacc, sxt, 4, rbase, sWz, sWr, sWw, 4, c0);
            // f-segment (K=64): all 3 gates
            gemmT3(zacc, racc, wacc, swk, 64, rbase,
                   sWz + 4 * 64, sWr + 4 * 64, sWw + 4 * 64, 64, c0);
            // h-segment (K=64): z and r only (w uses r*h later)
            gemmT2(zacc, racc, sh, 64, rbase,
                   sWz + 68 * 64, sWr + 68 * 64, 64, c0);
#pragma unroll
            for (int r = 0; r < 7; ++r) {
                upk2(zf[r][0], zf[r][1], zacc[r][0]);
                upk2(zf[r][2], zf[r][3], zacc[r][1]);
#pragma unroll
                for (int j = 0; j < 4; ++j) zf[r][j] = sigm(zf[r][j]);
            }
#pragma unroll
            for (int r = 0; r < 7; ++r) {
                upk2(rh[r][0], rh[r][1], racc[r][0]);
                upk2(rh[r][2], rh[r][3], racc[r][1]);
                float4 hv = *reinterpret_cast<const float4*>(sh + (rbase + r) * 64 + c0);
                rh[r][0] = sigm(rh[r][0]) * hv.x;
                rh[r][1] = sigm(rh[r][1]) * hv.y;
                rh[r][2] = sigm(rh[r][2]) * hv.z;
                rh[r][3] = sigm(rh[r][3]) * hv.w;
            }
        }

        __syncthreads();   // all reads of f and h (by other lanes) complete
        // write r*h over swk (pad rows stay zero: guarded)
#pragma unroll
        for (int r = 0; r < 7; ++r) {
            int row = rbase + r;
            if (row < NV)
                *reinterpret_cast<float4*>(swk + row * 64 + c0) =
                    make_float4(rh[r][0], rh[r][1], rh[r][2], rh[r][3]);
        }
        __syncthreads();

        // stage7: wpre += (r*h) @ Ww_h ; h = h + z*(tanh(wpre) - h)
        gemmT(wacc, swk, 64, rbase, sWw + 68 * 64, 64, c0);
#pragma unroll
        for (int r = 0; r < 7; ++r) {
            int row = rbase + r;
            if (row < NV) {
                float o0, o1, o2, o3;
                upk2(o0, o1, wacc[r][0]); upk2(o2, o3, wacc[r][1]);
                float* hp = sh + row * 64 + c0;
                float4 hv = *reinterpret_cast<const float4*>(hp);
                float n0 = hv.x + zf[r][0] * (tanh_fast(o0) - hv.x);
                float n1 = hv.y + zf[r][1] * (tanh_fast(o1) - hv.y);
                float n2 = hv.z + zf[r][2] * (tanh_fast(o2) - hv.z);
                float n3 = hv.w + zf[r][3] * (tanh_fast(o3) - hv.w);
                *reinterpret_cast<float4*>(hp) = make_float4(n0, n1, n2, n3);
            }
        }
        // top-of-loop barriers order h writes vs next reads
    }

    __syncthreads();
    for (int i = tid; i < NV * ND; i += 256)
        g_h[(size_t)b * (NV * ND) + i] = sh[i];
}

// ---------------- FC1: g_y = relu(g_h @ Wf1 + bf1), M=8192 K=6464 N=128 ----
__global__ __launch_bounds__(256, 2)
void fc1_kernel(const float* __restrict__ Wf1, const float* __restrict__ bf1)
{
    __shared__ float sA[64 * 16];
    __shared__ float sB[16 * 128];
    const int tid = threadIdx.x;
    const int m0  = blockIdx.x * 64;
    const int tn  = tid & 31;   // 0..31 -> 4 cols each
    const int tm  = tid >> 5;   // 0..7  -> 8 rows each

    float acc[8][4];
#pragma unroll
    for (int i = 0; i < 8; ++i)
#pragma unroll
        for (int j = 0; j < 4; ++j) acc[i][j] = 0.0f;

    const int ai = tid >> 2, ak = (tid & 3) * 4;
    const int bk = tid >> 4, bn = (tid & 15) * 8;

    for (int k0 = 0; k0 < NV * ND; k0 += 16) {
        *reinterpret_cast<float4*>(&sA[ai * 16 + ak]) =
            *reinterpret_cast<const float4*>(&g_h[(size_t)(m0 + ai) * (NV * ND) + k0 + ak]);
        *reinterpret_cast<float4*>(&sB[bk * 128 + bn]) =
            *reinterpret_cast<const float4*>(&Wf1[(size_t)(k0 + bk) * 128 + bn]);
        *reinterpret_cast<float4*>(&sB[bk * 128 + bn + 4]) =
            *reinterpret_cast<const float4*>(&Wf1[(size_t)(k0 + bk) * 128 + bn + 4]);
        __syncthreads();
#pragma unroll
        for (int kk = 0; kk < 16; ++kk) {
            float bv[4];
            *reinterpret_cast<float4*>(bv) =
                *reinterpret_cast<const float4*>(&sB[kk * 128 + tn * 4]);
#pragma unroll
            for (int i = 0; i < 8; ++i) {
                float av = sA[(tm * 8 + i) * 16 + kk];
                acc[i][0] = fmaf(av, bv[0], acc[i][0]);
                acc[i][1] = fmaf(av, bv[1], acc[i][1]);
                acc[i][2] = fmaf(av, bv[2], acc[i][2]);
                acc[i][3] = fmaf(av, bv[3], acc[i][3]);
            }
        }
        __syncthreads();
    }
#pragma unroll
    for (int i = 0; i < 8; ++i) {
        int m = m0 + tm * 8 + i;
#pragma unroll
        for (int j = 0; j < 4; ++j) {
            int n = tn * 4 + j;
            g_y[(size_t)m * 128 + n] = fmaxf(acc[i][j] + bf1[n], 0.0f);
        }
    }
}

// ---------------- head: out = softmax(g_y @ Wf2 + bf2) ----------------
__global__ __launch_bounds__(128)
void head_kernel(const float* __restrict__ Wf2, const float* __restrict__ bf2,
                 float* __restrict__ out)
{
    const int b = blockIdx.x, tid = threadIdx.x;
    __shared__ float sy[128];
    __shared__ float red[128];

    sy[tid] = g_y[(size_t)b * 128 + tid];
    __syncthreads();

    float logit = -3.0e38f;
    if (tid < NV) {
        float s = bf2[tid];
#pragma unroll 4
        for (int k = 0; k < 128; ++k) s = fmaf(sy[k], Wf2[k * NV + tid], s);
        logit = s;
    }
    red[tid] = logit;
    __syncthreads();
#pragma unroll
    for (int off = 64; off > 0; off >>= 1) {
        if (tid < off) red[tid] = fmaxf(red[tid], red[tid + off]);
        __syncthreads();
    }
    float m = red[0];
    __syncthreads();
    float e = (tid < NV) ? expf(logit - m) : 0.0f;
    red[tid] = e;
    __syncthreads();
#pragma unroll
    for (int off = 64; off > 0; off >>= 1) {
        if (tid < off) red[tid] += red[tid + off];
        __syncthreads();
    }
    float s = red[0];
    if (tid < NV) out[(size_t)b * NV + tid] = e / s;
}

extern "C" void kernel_launch(void* const* d_in, const int* in_sizes, int n_in,
                              void* d_out, int out_size)
{
    (void)in_sizes; (void)n_in; (void)out_size;
    const float* x   = (const float*)d_in[0];
    const float* dyn = (const float*)d_in[1];
    const float* W1  = (const float*)d_in[2];
    const float* b1  = (const float*)d_in[3];
    const float* W2  = (const float*)d_in[4];
    const float* b2  = (const float*)d_in[5];
    const float* Wz  = (const float*)d_in[6];
    const float* bz  = (const float*)d_in[7];
    const float* Wr  = (const float*)d_in[8];
    const float* br  = (const float*)d_in[9];
    const float* Ww  = (const float*)d_in[10];
    const float* bw  = (const float*)d_in[11];
    const float* Wf1 = (const float*)d_in[12];
    const float* bf1 = (const float*)d_in[13];
    const float* Wf2 = (const float*)d_in[14];
    const float* bf2 = (const float*)d_in[15];
    float* out = (float*)d_out;

    cudaFuncSetAttribute(mgcgru_scan, cudaFuncAttributeMaxDynamicSharedMemorySize, SMEM_BYTES);
    mgcgru_scan<<<NB, 256, SMEM_BYTES>>>(x, dyn, W1, b1, W2, b2, Wz, bz, Wr, br, Ww, bw);
    fc1_kernel<<<NB / 64, 256>>>(Wf1, bf1);
    head_kernel<<<NB, 128>>>(Wf2, bf2, out);
}